// round 2
// baseline (speedup 1.0000x reference)
#include <cuda_runtime.h>
#include <math.h>

#define BATCH 512
#define HID   512
#define NCLS  1000
#define MC    4000
#define INV_SIGMA (1.0f/10.0f)

// ---------------- scratch (static device globals; no allocations) ----------------
__device__ __align__(16) float g_a[MC];        // ||w_m||^2
__device__ __align__(16) float g_fsq[BATCH];   // ||f_b||^2
__device__ __align__(16) float g_s[HID];       // column sums of W
__device__ __align__(16) float g_sp[8][HID];   // partial column sums
__device__ __align__(16) float g_Gp[5][HID*HID]; // partial Gram (m-chunks of 800)
__device__ double g_sum_a, g_sum_a2, g_sum_at, g_F2, g_s2;

// ---------------- init scalars ----------------
__global__ void k_init() {
    g_sum_a = 0.0; g_sum_a2 = 0.0; g_sum_at = 0.0; g_F2 = 0.0; g_s2 = 0.0;
}

// ---------------- column sums: s[k] = sum_m W[m,k] ----------------
__global__ void k_colsum_part(const float* __restrict__ W) {
    int k  = threadIdx.x;                // 512 threads
    int m0 = blockIdx.x * 500;           // 8 blocks
    float s = 0.f;
    #pragma unroll 4
    for (int m = 0; m < 500; m++) s += W[(size_t)(m0 + m) * HID + k];
    g_sp[blockIdx.x][k] = s;
}

__global__ void k_colsum_reduce() {
    __shared__ double red[512];
    int k = threadIdx.x;
    float s = 0.f;
    #pragma unroll
    for (int j = 0; j < 8; j++) s += g_sp[j][k];
    g_s[k] = s;
    red[k] = (double)s * (double)s;
    __syncthreads();
    for (int o = 256; o > 0; o >>= 1) {
        if (k < o) red[k] += red[k + o];
        __syncthreads();
    }
    if (k == 0) g_s2 = red[0];
}

// ---------------- per-row: a_m = ||w_m||^2, t_m = w_m . s ; f_sq ----------------
// rows 0..3999 -> W, rows 4000..4511 -> f
__global__ void k_rows(const float* __restrict__ W, const float* __restrict__ F) {
    int warp = (blockIdx.x * blockDim.x + threadIdx.x) >> 5;
    int lane = threadIdx.x & 31;
    bool isW = (warp < MC);
    const float* row = isW ? (W + (size_t)warp * HID)
                           : (F + (size_t)(warp - MC) * HID);
    float a = 0.f, t = 0.f;
    #pragma unroll
    for (int q = 0; q < 4; q++) {
        int i4 = lane + q * 32;
        float4 v = reinterpret_cast<const float4*>(row)[i4];
        a += v.x*v.x + v.y*v.y + v.z*v.z + v.w*v.w;
        if (isW) {
            float4 sv = reinterpret_cast<const float4*>(g_s)[i4];
            t += v.x*sv.x + v.y*sv.y + v.z*sv.z + v.w*sv.w;
        }
    }
    #pragma unroll
    for (int o = 16; o > 0; o >>= 1) {
        a += __shfl_down_sync(0xffffffffu, a, o);
        t += __shfl_down_sync(0xffffffffu, t, o);
    }
    if (lane == 0) {
        if (isW) {
            g_a[warp] = a;
            atomicAdd(&g_sum_a,  (double)a);
            atomicAdd(&g_sum_a2, (double)a * (double)a);
            atomicAdd(&g_sum_at, (double)a * (double)t);
        } else {
            g_fsq[warp - MC] = a;
        }
    }
}

// ---------------- Gram partials: G = W^T W, split into 5 m-chunks of 800 ----------------
// grid (8,8,5), block (16,16). Tile 64x64 over (k,l).
__global__ void __launch_bounds__(256) k_gram(const float* __restrict__ W) {
    __shared__ float As[32][64];
    __shared__ float Bs[32][64];
    int K0 = blockIdx.x * 64, L0 = blockIdx.y * 64;
    int mz = blockIdx.z;
    int tx = threadIdx.x, ty = threadIdx.y;
    int tid = ty * 16 + tx;
    float acc[4][4] = {};
    int m0 = mz * 800;
    for (int mm = 0; mm < 800; mm += 32) {
        __syncthreads();
        #pragma unroll
        for (int p = 0; p < 2; p++) {
            int idx = tid + p * 256;
            int r = idx >> 4, c4 = idx & 15;
            const float* base = W + (size_t)(m0 + mm + r) * HID;
            float4 va = *reinterpret_cast<const float4*>(base + K0 + c4 * 4);
            float4 vb = *reinterpret_cast<const float4*>(base + L0 + c4 * 4);
            *reinterpret_cast<float4*>(&As[r][c4 * 4]) = va;
            *reinterpret_cast<float4*>(&Bs[r][c4 * 4]) = vb;
        }
        __syncthreads();
        #pragma unroll
        for (int kk = 0; kk < 32; kk++) {
            float4 av = *reinterpret_cast<const float4*>(&As[kk][ty * 4]);
            float4 bv = *reinterpret_cast<const float4*>(&Bs[kk][tx * 4]);
            float aa[4] = {av.x, av.y, av.z, av.w};
            float bb[4] = {bv.x, bv.y, bv.z, bv.w};
            #pragma unroll
            for (int i = 0; i < 4; i++)
                #pragma unroll
                for (int j = 0; j < 4; j++)
                    acc[i][j] += aa[i] * bb[j];
        }
    }
    float* dst = g_Gp[mz];
    #pragma unroll
    for (int i = 0; i < 4; i++)
        #pragma unroll
        for (int j = 0; j < 4; j++)
            dst[(size_t)(K0 + ty * 4 + i) * HID + L0 + tx * 4 + j] = acc[i][j];
}

// ---------------- F2 = ||G||_F^2 ----------------
__global__ void k_f2() {
    double acc = 0.0;
    for (int i = blockIdx.x * blockDim.x + threadIdx.x; i < HID * HID;
         i += gridDim.x * blockDim.x) {
        float g = g_Gp[0][i] + g_Gp[1][i] + g_Gp[2][i] + g_Gp[3][i] + g_Gp[4][i];
        acc += (double)g * (double)g;
    }
    __shared__ double sd[256];
    sd[threadIdx.x] = acc;
    __syncthreads();
    for (int o = 128; o > 0; o >>= 1) {
        if (threadIdx.x < o) sd[threadIdx.x] += sd[threadIdx.x + o];
        __syncthreads();
    }
    if (threadIdx.x == 0) atomicAdd(&g_F2, sd[0]);
}

// ---------------- main GEMM fw = f.W^T + fused distance epilogue ----------------
// grid (32,4) over (m-tiles, b-tiles); block (16,16); 128x128 tile, 8x8 micro, BK=16.
__global__ void __launch_bounds__(256) k_fw(const float* __restrict__ F,
                                            const float* __restrict__ W,
                                            float* __restrict__ out) {
    __shared__ float Af[16][132];
    __shared__ float Bf[16][132];
    int m0 = blockIdx.x * 128;
    int b0 = blockIdx.y * 128;
    int tx = threadIdx.x, ty = threadIdx.y;
    int tid = ty * 16 + tx;
    float acc[8][8] = {};

    for (int k0 = 0; k0 < HID; k0 += 16) {
        __syncthreads();
        #pragma unroll
        for (int p = 0; p < 2; p++) {
            int idx = tid + p * 256;
            int r = idx >> 2, c4 = idx & 3;
            float4 v = *reinterpret_cast<const float4*>(
                F + (size_t)(b0 + r) * HID + k0 + c4 * 4);
            Af[c4 * 4 + 0][r] = v.x; Af[c4 * 4 + 1][r] = v.y;
            Af[c4 * 4 + 2][r] = v.z; Af[c4 * 4 + 3][r] = v.w;
            int m = m0 + r;
            float4 w = make_float4(0.f, 0.f, 0.f, 0.f);
            if (m < MC)
                w = *reinterpret_cast<const float4*>(
                    W + (size_t)m * HID + k0 + c4 * 4);
            Bf[c4 * 4 + 0][r] = w.x; Bf[c4 * 4 + 1][r] = w.y;
            Bf[c4 * 4 + 2][r] = w.z; Bf[c4 * 4 + 3][r] = w.w;
        }
        __syncthreads();
        #pragma unroll
        for (int kk = 0; kk < 16; kk++) {
            float4 a0 = *reinterpret_cast<const float4*>(&Af[kk][ty * 4]);
            float4 a1 = *reinterpret_cast<const float4*>(&Af[kk][64 + ty * 4]);
            float4 bb0 = *reinterpret_cast<const float4*>(&Bf[kk][tx * 4]);
            float4 bb1 = *reinterpret_cast<const float4*>(&Bf[kk][64 + tx * 4]);
            float aa[8] = {a0.x, a0.y, a0.z, a0.w, a1.x, a1.y, a1.z, a1.w};
            float bb[8] = {bb0.x, bb0.y, bb0.z, bb0.w, bb1.x, bb1.y, bb1.z, bb1.w};
            #pragma unroll
            for (int i = 0; i < 8; i++)
                #pragma unroll
                for (int j = 0; j < 8; j++)
                    acc[i][j] += aa[i] * bb[j];
        }
    }

    // epilogue: out[b, g] = exp(-(fsq[b] + min_{4 centers}(a_m - 2 fw)) / sigma)
    #pragma unroll
    for (int jh = 0; jh < 2; jh++) {
        int mb = m0 + jh * 64 + tx * 4;   // 4 consecutive m = one class group
        if (mb >= MC) continue;
        float a0 = g_a[mb + 0], a1 = g_a[mb + 1];
        float a2 = g_a[mb + 2], a3 = g_a[mb + 3];
        int grp = mb >> 2;
        #pragma unroll
        for (int ih = 0; ih < 2; ih++) {
            #pragma unroll
            for (int ii = 0; ii < 4; ii++) {
                int i = ih * 4 + ii;
                int b = b0 + ih * 64 + ty * 4 + ii;
                float x0 = a0 - 2.f * acc[i][jh * 4 + 0];
                float x1 = a1 - 2.f * acc[i][jh * 4 + 1];
                float x2 = a2 - 2.f * acc[i][jh * 4 + 2];
                float x3 = a3 - 2.f * acc[i][jh * 4 + 3];
                float xm = fminf(fminf(x0, x1), fminf(x2, x3));
                out[(size_t)b * (NCLS + 1) + grp] =
                    expf(-(g_fsq[b] + xm) * INV_SIGMA);
            }
        }
    }
}

// ---------------- finalize rw and write last column ----------------
__global__ void k_finalize(float* __restrict__ out) {
    __shared__ float rw_s;
    if (threadIdx.x == 0) {
        double sum_a = g_sum_a, sum_a2 = g_sum_a2, sum_at = g_sum_at;
        double F2 = g_F2, s2 = g_s2;
        double mc = (double)MC;
        double denom = 2.0 / (mc * mc - mc);
        double S1 = mc * sum_a - s2;
        double mu = denom * S1;
        double S2 = mc * sum_a2 + sum_a * sum_a + 2.0 * F2 - 4.0 * sum_at;
        rw_s = (float)(denom * S2 - mu * mu);
    }
    __syncthreads();
    out[(size_t)threadIdx.x * (NCLS + 1) + NCLS] = rw_s;
}

extern "C" void kernel_launch(void* const* d_in, const int* in_sizes, int n_in,
                              void* d_out, int out_size) {
    const float* F = (const float*)d_in[0];   // [512,512]
    const float* W = (const float*)d_in[1];   // [1000,4,512] -> [4000,512]
    float* out = (float*)d_out;               // [512,1001]
    (void)in_sizes; (void)n_in; (void)out_size;

    k_init<<<1, 1>>>();
    k_colsum_part<<<8, 512>>>(W);
    k_colsum_reduce<<<1, 512>>>();
    k_rows<<<564, 256>>>(W, F);
    k_gram<<<dim3(8, 8, 5), dim3(16, 16)>>>(W);
    k_f2<<<256, 256>>>();
    k_fw<<<dim3(32, 4), dim3(16, 16)>>>(F, W, out);
    k_finalize<<<1, 512>>>(out);
}

// round 6
// speedup vs baseline: 1.8257x; 1.8257x over previous
#include <cuda_runtime.h>
#include <math.h>
#include <stdint.h>

#define BATCH 512
#define HID   512
#define NCLS  1000
#define MC    4000
#define INV_SIGMA (1.0f/10.0f)

#if defined(__CUDA_ARCH__) && (__CUDA_ARCH__ == 1030) && defined(__CUDA_ARCH_FEAT_SM103_ALL)
#define HAS_TC 1
#else
#define HAS_TC 0
#endif

// ---------------- scratch ----------------
__device__ __align__(16) float g_a[4096];      // ||w_m||^2
__device__ __align__(16) float g_fsq[BATCH];   // ||f_b||^2
__device__ __align__(16) float g_s[HID];       // column sums of W
__device__ __align__(16) float g_sp[8][HID];   // partial column sums
// Gram partials: 10 (k<=l) tiles x 15 m-chunks x 128x128
__device__ __align__(16) float g_G2[10*15*16384];
__device__ double g_sum_a, g_sum_a2, g_sum_at, g_F2, g_s2;

__constant__ int c_ti[10] = {0,0,0,0,1,1,1,2,2,3};
__constant__ int c_tj[10] = {0,1,2,3,1,2,3,2,3,3};

// ---------------- PTX helpers ----------------
__device__ __forceinline__ uint32_t smem_u32(const void* p) {
    uint32_t a;
    asm("{ .reg .u64 t; cvta.to.shared.u64 t, %1; cvt.u32.u64 %0, t; }"
        : "=r"(a) : "l"(p));
    return a;
}
__device__ __forceinline__ uint32_t elect_one() {
    uint32_t pred;
    asm volatile("{\n\t.reg .pred p;\n\telect.sync _|p, 0xFFFFFFFF;\n\t"
                 "selp.b32 %0, 1, 0, p;\n\t}" : "=r"(pred));
    return pred;
}
#define MBAR_INIT(addr, cnt) \
    asm volatile("mbarrier.init.shared.b64 [%0], %1;" :: "r"(addr), "r"(cnt) : "memory")
#define MBAR_WAIT(addr, par) do { \
    uint32_t _m = (addr), _p = (par), _d; \
    asm volatile("{\n\t.reg .pred p;\n\t" \
        "mbarrier.try_wait.parity.acquire.cta.shared::cta.b64 p, [%1], %2;\n\t" \
        "selp.b32 %0, 1, 0, p;\n\t}" : "=r"(_d) : "r"(_m), "r"(_p) : "memory"); \
    if (!_d) { \
        asm volatile("{\n\t.reg .pred P1;\n\tWL%=:\n\t" \
            "mbarrier.try_wait.parity.acquire.cta.shared::cta.b64 P1, [%0], %1, 0x989680;\n\t" \
            "@P1 bra.uni WD%=;\n\tbra.uni WL%=;\n\tWD%=:\n\t}" \
            :: "r"(_m), "r"(_p) : "memory"); \
    } } while (0)

#if HAS_TC
#define TC_ALLOC(smem_addr, n) \
    asm volatile("tcgen05.alloc.cta_group::1.sync.aligned.shared::cta.b32 [%0], %1;" \
        :: "r"(smem_addr), "r"(n) : "memory")
#define TC_DEALLOC(tmem, n) \
    asm volatile("tcgen05.dealloc.cta_group::1.sync.aligned.b32 %0, %1;" :: "r"(tmem), "r"(n))
#define TC_RELINQ() \
    asm volatile("tcgen05.relinquish_alloc_permit.cta_group::1.sync.aligned;")
#define TC_COMMIT(mbar) \
    asm volatile("tcgen05.commit.cta_group::1.mbarrier::arrive::one.shared::cluster.b64 [%0];" \
        :: "r"(mbar) : "memory")
#define TC_FENCE_AFTER() asm volatile("tcgen05.fence::after_thread_sync;" ::: "memory")
#define TC_FENCE_BEFORE() asm volatile("tcgen05.fence::before_thread_sync;" ::: "memory")
#define TC_WAIT_LD() asm volatile("tcgen05.wait::ld.sync.aligned;" ::: "memory")
#define LDTM_X32(r, addr) \
    asm volatile("tcgen05.ld.sync.aligned.32x32b.x32.b32 " \
        "{%0,%1,%2,%3,%4,%5,%6,%7,%8,%9,%10,%11,%12,%13,%14,%15," \
        "%16,%17,%18,%19,%20,%21,%22,%23,%24,%25,%26,%27,%28,%29,%30,%31}, [%32];" \
        : "=r"((r)[0]),"=r"((r)[1]),"=r"((r)[2]),"=r"((r)[3]), \
          "=r"((r)[4]),"=r"((r)[5]),"=r"((r)[6]),"=r"((r)[7]), \
          "=r"((r)[8]),"=r"((r)[9]),"=r"((r)[10]),"=r"((r)[11]), \
          "=r"((r)[12]),"=r"((r)[13]),"=r"((r)[14]),"=r"((r)[15]), \
          "=r"((r)[16]),"=r"((r)[17]),"=r"((r)[18]),"=r"((r)[19]), \
          "=r"((r)[20]),"=r"((r)[21]),"=r"((r)[22]),"=r"((r)[23]), \
          "=r"((r)[24]),"=r"((r)[25]),"=r"((r)[26]),"=r"((r)[27]), \
          "=r"((r)[28]),"=r"((r)[29]),"=r"((r)[30]),"=r"((r)[31]) \
        : "r"(addr))

// SW128 K-major desc: LBO=1, SBO=64, version=1, layout=2
static __device__ __forceinline__ uint64_t make_desc(uint32_t addr) {
    const uint64_t base = (uint64_t(2) << 61) | (uint64_t(1) << 46)
                        | (uint64_t(64) << 32) | (uint64_t(1) << 16);
    return base | ((uint64_t)(addr >> 4) & 0x3FFF);
}
// tf32 SS MMA, cg1: D[128,128] += A[128,8] * B[128,8]^T
__device__ __forceinline__ void mma_tf32(uint32_t d, uint64_t ad, uint64_t bd,
                                         uint32_t idesc, uint32_t en) {
    asm volatile("{\n\t.reg .pred p;\n\tsetp.ne.u32 p, %5, 0;\n\t"
        "tcgen05.mma.cta_group::1.kind::tf32 [%0], %1, %2, %3, {%4,%4,%4,%4}, p;\n\t}"
        :: "r"(d), "l"(ad), "l"(bd), "r"(idesc), "r"(0u), "r"(en) : "memory");
}
#endif  // HAS_TC

__device__ __forceinline__ uint32_t swz(uint32_t o) { return o ^ ((o >> 3) & 0x70); }

__device__ __forceinline__ void cp16(uint32_t dst, const void* src, bool valid) {
    int sz = valid ? 16 : 0;
    asm volatile("cp.async.cg.shared.global [%0], [%1], 16, %2;"
                 :: "r"(dst), "l"(src), "r"(sz));
}

// ---------------- small kernels ----------------
__global__ void k_init() {
    g_sum_a = 0.0; g_sum_a2 = 0.0; g_sum_at = 0.0; g_F2 = 0.0; g_s2 = 0.0;
}

__global__ void k_colsum_part(const float* __restrict__ W) {
    int k  = threadIdx.x;
    int m0 = blockIdx.x * 500;
    float s = 0.f;
    #pragma unroll 4
    for (int m = 0; m < 500; m++) s += W[(size_t)(m0 + m) * HID + k];
    g_sp[blockIdx.x][k] = s;
}

__global__ void k_colsum_reduce() {
    __shared__ double red[512];
    int k = threadIdx.x;
    float s = 0.f;
    #pragma unroll
    for (int j = 0; j < 8; j++) s += g_sp[j][k];
    g_s[k] = s;
    red[k] = (double)s * (double)s;
    __syncthreads();
    for (int o = 256; o > 0; o >>= 1) {
        if (k < o) red[k] += red[k + o];
        __syncthreads();
    }
    if (k == 0) g_s2 = red[0];
}

__global__ void k_rows(const float* __restrict__ W, const float* __restrict__ F) {
    int warp = (blockIdx.x * blockDim.x + threadIdx.x) >> 5;
    int lane = threadIdx.x & 31;
    bool isW = (warp < MC);
    const float* row = isW ? (W + (size_t)warp * HID)
                           : (F + (size_t)(warp - MC) * HID);
    float a = 0.f, t = 0.f;
    #pragma unroll
    for (int q = 0; q < 4; q++) {
        int i4 = lane + q * 32;
        float4 v = reinterpret_cast<const float4*>(row)[i4];
        a += v.x*v.x + v.y*v.y + v.z*v.z + v.w*v.w;
        if (isW) {
            float4 sv = reinterpret_cast<const float4*>(g_s)[i4];
            t += v.x*sv.x + v.y*sv.y + v.z*sv.z + v.w*sv.w;
        }
    }
    #pragma unroll
    for (int o = 16; o > 0; o >>= 1) {
        a += __shfl_down_sync(0xffffffffu, a, o);
        t += __shfl_down_sync(0xffffffffu, t, o);
    }
    if (lane == 0) {
        if (isW) {
            g_a[warp] = a;
            atomicAdd(&g_sum_a,  (double)a);
            atomicAdd(&g_sum_a2, (double)a * (double)a);
            atomicAdd(&g_sum_at, (double)a * (double)t);
        } else {
            g_fsq[warp - MC] = a;
        }
    }
}

// ---------------- Gram (FFMA, symmetric tiles, 8x8 micro) ----------------
// grid (10, 15): 10 (ti<=tj) 128x128 tiles, 15 m-chunks of 272 (last 192)
__global__ void __launch_bounds__(256) k_gram2(const float* __restrict__ W) {
    __shared__ float As[16][132];
    __shared__ float Bs[16][132];
    int t = blockIdx.x, z = blockIdx.y;
    int K0 = c_ti[t] * 128, L0 = c_tj[t] * 128;
    int m0 = z * 272;
    int len = min(272, MC - m0);
    int tx = threadIdx.x & 15, ty = threadIdx.x >> 4;
    int tid = threadIdx.x;
    float acc[8][8] = {};

    for (int mm = 0; mm < len; mm += 16) {
        __syncthreads();
        #pragma unroll
        for (int p = 0; p < 2; p++) {
            int idx = tid + p * 256;
            int r = idx >> 5, c4 = idx & 31;
            const float* base = W + (size_t)(m0 + mm + r) * HID;
            *reinterpret_cast<float4*>(&As[r][c4 * 4]) =
                *reinterpret_cast<const float4*>(base + K0 + c4 * 4);
            *reinterpret_cast<float4*>(&Bs[r][c4 * 4]) =
                *reinterpret_cast<const float4*>(base + L0 + c4 * 4);
        }
        __syncthreads();
        #pragma unroll
        for (int kk = 0; kk < 16; kk++) {
            float4 a0 = *reinterpret_cast<const float4*>(&As[kk][ty * 4]);
            float4 a1 = *reinterpret_cast<const float4*>(&As[kk][64 + ty * 4]);
            float4 b0 = *reinterpret_cast<const float4*>(&Bs[kk][tx * 4]);
            float4 b1 = *reinterpret_cast<const float4*>(&Bs[kk][64 + tx * 4]);
            float aa[8] = {a0.x,a0.y,a0.z,a0.w,a1.x,a1.y,a1.z,a1.w};
            float bb[8] = {b0.x,b0.y,b0.z,b0.w,b1.x,b1.y,b1.z,b1.w};
            #pragma unroll
            for (int i = 0; i < 8; i++)
                #pragma unroll
                for (int j = 0; j < 8; j++)
                    acc[i][j] += aa[i] * bb[j];
        }
    }
    float* dst = g_G2 + ((size_t)(t * 15 + z) << 14);
    #pragma unroll
    for (int ih = 0; ih < 2; ih++)
        #pragma unroll
        for (int i = 0; i < 4; i++) {
            int row = ih * 64 + ty * 4 + i;
            #pragma unroll
            for (int jh = 0; jh < 2; jh++)
                *reinterpret_cast<float4*>(&dst[row * 128 + jh * 64 + tx * 4]) =
                    make_float4(acc[ih*4+i][jh*4+0], acc[ih*4+i][jh*4+1],
                                acc[ih*4+i][jh*4+2], acc[ih*4+i][jh*4+3]);
        }
}

// ---------------- F2 = ||G||_F^2 (with symmetry weights) ----------------
__global__ void k_f2() {
    double acc = 0.0;
    for (int i = blockIdx.x * blockDim.x + threadIdx.x; i < 10 * 16384;
         i += gridDim.x * blockDim.x) {
        int t = i >> 14, e = i & 16383;
        float g = 0.f;
        #pragma unroll
        for (int z = 0; z < 15; z++) g += g_G2[((size_t)(t * 15 + z) << 14) + e];
        double w = (c_ti[t] == c_tj[t]) ? 1.0 : 2.0;
        acc += w * (double)g * (double)g;
    }
    __shared__ double sd[256];
    sd[threadIdx.x] = acc;
    __syncthreads();
    for (int o = 128; o > 0; o >>= 1) {
        if (threadIdx.x < o) sd[threadIdx.x] += sd[threadIdx.x + o];
        __syncthreads();
    }
    if (threadIdx.x == 0) atomicAdd(&g_F2, sd[0]);
}

// ---------------- tcgen05 tf32 GEMM: fw = W . F^T + fused epilogue ----------------
// grid (32, 4): m-tiles x b-tiles. 128 threads. D[128(m),128(b)] in TMEM.
#define KC      32          // fp32 per K-chunk (128 bytes/row)
#define NCHUNK  16          // 512 / 32
#define STG     4
#define STG_BYTES 16384     // 128 rows x 128B
#define OFF_A   1024
#define OFF_B   (1024 + STG*STG_BYTES)
#define SMEM_FW (1024 + 2*STG*STG_BYTES)
// idesc: cF32 | aTF32 | bTF32 | N=128 | M=128
#define IDESC_TF32 ((1u<<4) | (2u<<7) | (2u<<10) | (16u<<17) | (8u<<24))

__device__ __forceinline__ void fw_load_chunk(uint32_t sb, int stage, int c,
                                              const float* __restrict__ W,
                                              const float* __restrict__ F,
                                              int m0, int b0, int tid) {
    int kc = c * KC;
    uint32_t dA = sb + OFF_A + stage * STG_BYTES;
    uint32_t dB = sb + OFF_B + stage * STG_BYTES;
    #pragma unroll
    for (int p = 0; p < 8; p++) {
        int idx = p * 128 + tid;
        int r = idx >> 3, seg = idx & 7;
        uint32_t off = swz((uint32_t)(r * 128 + seg * 16));
        int m = m0 + r;
        bool v = (m < MC);
        cp16(dA + off, W + (size_t)(v ? m : 0) * HID + kc + seg * 4, v);
        cp16(dB + off, F + (size_t)(b0 + r) * HID + kc + seg * 4, true);
    }
}

__global__ void __launch_bounds__(128, 1) k_fw_tc(const float* __restrict__ F,
                                                  const float* __restrict__ W,
                                                  float* __restrict__ out) {
#if HAS_TC
    extern __shared__ char smem[];
    uint32_t sb = smem_u32(smem);
    int tid = threadIdx.x, wid = tid >> 5, lane = tid & 31;
    int m0 = blockIdx.x * 128, b0 = blockIdx.y * 128;

    if (tid < 4) MBAR_INIT(sb + tid * 8, 1);       // mma_bar[0..3] at 0..31
    if (wid == 0) { TC_ALLOC(sb + 32, 128); TC_RELINQ(); }
    __syncthreads();
    uint32_t tmem;
    asm volatile("ld.shared.b32 %0, [%1];" : "=r"(tmem) : "r"(sb + 32));

    // prologue: chunks 0..2 -> stages 0..2
    #pragma unroll
    for (int c0 = 0; c0 < 3; c0++) {
        fw_load_chunk(sb, c0, c0, W, F, m0, b0, tid);
        asm volatile("cp.async.commit_group;" ::: "memory");
    }

    uint32_t phv = 0;
    for (int c = 0; c < NCHUNK; c++) {
        int s = c & 3;
        if (c + 3 < NCHUNK) {
            int so = (c + 3) & 3;
            if (c >= 1) {                       // stage reuse: wait MMAs of chunk c-1
                MBAR_WAIT(sb + so * 8, (phv >> so) & 1u);
                phv ^= (1u << so);
            }
            fw_load_chunk(sb, so, c + 3, W, F, m0, b0, tid);
        }
        asm volatile("cp.async.commit_group;" ::: "memory");
        asm volatile("cp.async.wait_group 3;" ::: "memory");
        __syncthreads();
        if (wid == 0 && elect_one()) {
            asm volatile("fence.proxy.async.shared::cta;" ::: "memory");
            uint64_t ad = make_desc(sb + OFF_A + s * STG_BYTES);
            uint64_t bd = make_desc(sb + OFF_B + s * STG_BYTES);
            #pragma unroll
            for (int k = 0; k < 4; k++)
                mma_tf32(tmem, ad + k * 2, bd + k * 2, IDESC_TF32,
                         (c > 0 || k > 0) ? 1u : 0u);
            TC_COMMIT(sb + s * 8);
        }
    }
    __syncthreads();
    MBAR_WAIT(sb + 3 * 8, (phv >> 3) & 1u);   // chunk 15 commit = all MMAs done
    TC_FENCE_AFTER();

    // epilogue: x = a_m - 2*fw ; min over 4-lane quads ; exp
    int m = m0 + wid * 32 + lane;
    float a = (m < MC) ? __ldg(&g_a[m]) : __int_as_float(0x7f800000);
    int grp = m >> 2;
    #pragma unroll
    for (int j0 = 0; j0 < 128; j0 += 32) {
        uint32_t r[32];
        LDTM_X32(r, tmem + j0);
        TC_WAIT_LD();
        #pragma unroll
        for (int jj = 0; jj < 32; jj++) {
            float fw = __uint_as_float(r[jj]);
            float x = fmaf(-2.f, fw, a);
            x = fminf(x, __shfl_xor_sync(0xffffffffu, x, 1));
            x = fminf(x, __shfl_xor_sync(0xffffffffu, x, 2));
            if ((lane & 3) == 0 && m < MC) {
                int b = b0 + j0 + jj;
                out[(size_t)b * (NCLS + 1) + grp] =
                    expf(-(__ldg(&g_fsq[b]) + x) * INV_SIGMA);
            }
        }
    }
    TC_FENCE_BEFORE();
    __syncthreads();
    if (wid == 0) TC_DEALLOC(tmem, 128);
#else
    // Correct (slow) fallback for non-sm_103a images: never selected on GB300
    // (the exact-match sm_103a cubin is preferred), but keeps every fatbin
    // stage compilable AND correct.
    int tid = threadIdx.x;
    int m0 = blockIdx.x * 128, b0 = blockIdx.y * 128;
    int m = m0 + tid;
    if (m >= MC) return;
    float a = g_a[m];
    int grp = m >> 2;
    const float* wrow = W + (size_t)m * HID;
    for (int jb = 0; jb < 128; jb++) {
        int b = b0 + jb;
        const float* frow = F + (size_t)b * HID;
        float dot = 0.f;
        for (int k = 0; k < HID; k++) dot = fmaf(wrow[k], frow[k], dot);
        float x = fmaf(-2.f, dot, a);
        x = fminf(x, __shfl_xor_sync(0xffffffffu, x, 1));
        x = fminf(x, __shfl_xor_sync(0xffffffffu, x, 2));
        if ((tid & 3) == 0)
            out[(size_t)b * (NCLS + 1) + grp] =
                expf(-(g_fsq[b] + x) * INV_SIGMA);
    }
#endif
}

// ---------------- finalize rw ----------------
__global__ void k_finalize(float* __restrict__ out) {
    __shared__ float rw_s;
    if (threadIdx.x == 0) {
        double sum_a = g_sum_a, sum_a2 = g_sum_a2, sum_at = g_sum_at;
        double F2 = g_F2, s2 = g_s2;
        double mc = (double)MC;
        double denom = 2.0 / (mc * mc - mc);
        double S1 = mc * sum_a - s2;
        double mu = denom * S1;
        double S2 = mc * sum_a2 + sum_a * sum_a + 2.0 * F2 - 4.0 * sum_at;
        rw_s = (float)(denom * S2 - mu * mu);
    }
    __syncthreads();
    out[(size_t)threadIdx.x * (NCLS + 1) + NCLS] = rw_s;
}

extern "C" void kernel_launch(void* const* d_in, const int* in_sizes, int n_in,
                              void* d_out, int out_size) {
    const float* F = (const float*)d_in[0];   // [512,512]
    const float* W = (const float*)d_in[1];   // [4000,512]
    float* out = (float*)d_out;               // [512,1001]
    (void)in_sizes; (void)n_in; (void)out_size;

    static bool attr_set = false;
    if (!attr_set) {
        cudaFuncSetAttribute(k_fw_tc, cudaFuncAttributeMaxDynamicSharedMemorySize,
                             SMEM_FW);
        attr_set = true;
    }

    k_init<<<1, 1>>>();
    k_colsum_part<<<8, 512>>>(W);
    k_colsum_reduce<<<1, 512>>>();
    k_rows<<<564, 256>>>(W, F);
    k_gram2<<<dim3(10, 15), 256>>>(W);
    k_f2<<<160, 256>>>();
    k_fw_tc<<<dim3(32, 4), 128, SMEM_FW>>>(F, W, out);
    k_finalize<<<1, 512>>>(out);
}

// round 7
// speedup vs baseline: 3.1664x; 1.7344x over previous
#include <cuda_runtime.h>
#include <math.h>
#include <stdint.h>

#define BATCH 512
#define HID   512
#define NCLS  1000
#define MC    4000
#define INV_SIGMA (1.0f/10.0f)

#if defined(__CUDA_ARCH__) && (__CUDA_ARCH__ == 1030) && defined(__CUDA_ARCH_FEAT_SM103_ALL)
#define HAS_TC 1
#else
#define HAS_TC 0
#endif

// ---------------- scratch ----------------
__device__ __align__(16) float g_a[4096];        // ||w_m||^2
__device__ __align__(16) float g_fsq[BATCH];     // ||f_b||^2
__device__ __align__(16) float g_s[HID];         // column sums of W
__device__ __align__(16) float g_sp[80][HID];    // partial column sums
__device__ __align__(16) float g_Wt[512*4096];   // W transposed, padded stride 4096
// Gram partials: 10 (ti<=tj) tiles x 5 m-chunks x 128x128
__device__ __align__(16) float g_G2[10*5*16384];
__device__ double g_sum_a, g_sum_a2, g_sum_at, g_F2, g_s2;

__constant__ int c_ti[10] = {0,0,0,0,1,1,1,2,2,3};
__constant__ int c_tj[10] = {0,1,2,3,1,2,3,2,3,3};

// ---------------- PTX helpers ----------------
__device__ __forceinline__ uint32_t smem_u32(const void* p) {
    uint32_t a;
    asm("{ .reg .u64 t; cvta.to.shared.u64 t, %1; cvt.u32.u64 %0, t; }"
        : "=r"(a) : "l"(p));
    return a;
}
__device__ __forceinline__ uint32_t elect_one() {
    uint32_t pred;
    asm volatile("{\n\t.reg .pred p;\n\telect.sync _|p, 0xFFFFFFFF;\n\t"
                 "selp.b32 %0, 1, 0, p;\n\t}" : "=r"(pred));
    return pred;
}
#define MBAR_INIT(addr, cnt) \
    asm volatile("mbarrier.init.shared.b64 [%0], %1;" :: "r"(addr), "r"(cnt) : "memory")
#define MBAR_WAIT(addr, par) do { \
    uint32_t _m = (addr), _p = (par), _d; \
    asm volatile("{\n\t.reg .pred p;\n\t" \
        "mbarrier.try_wait.parity.acquire.cta.shared::cta.b64 p, [%1], %2;\n\t" \
        "selp.b32 %0, 1, 0, p;\n\t}" : "=r"(_d) : "r"(_m), "r"(_p) : "memory"); \
    if (!_d) { \
        asm volatile("{\n\t.reg .pred P1;\n\tWL%=:\n\t" \
            "mbarrier.try_wait.parity.acquire.cta.shared::cta.b64 P1, [%0], %1, 0x989680;\n\t" \
            "@P1 bra.uni WD%=;\n\tbra.uni WL%=;\n\tWD%=:\n\t}" \
            :: "r"(_m), "r"(_p) : "memory"); \
    } } while (0)

#if HAS_TC
#define TC_ALLOC(smem_addr, n) \
    asm volatile("tcgen05.alloc.cta_group::1.sync.aligned.shared::cta.b32 [%0], %1;" \
        :: "r"(smem_addr), "r"(n) : "memory")
#define TC_DEALLOC(tmem, n) \
    asm volatile("tcgen05.dealloc.cta_group::1.sync.aligned.b32 %0, %1;" :: "r"(tmem), "r"(n))
#define TC_RELINQ() \
    asm volatile("tcgen05.relinquish_alloc_permit.cta_group::1.sync.aligned;")
#define TC_COMMIT(mbar) \
    asm volatile("tcgen05.commit.cta_group::1.mbarrier::arrive::one.shared::cluster.b64 [%0];" \
        :: "r"(mbar) : "memory")
#define TC_FENCE_AFTER() asm volatile("tcgen05.fence::after_thread_sync;" ::: "memory")
#define TC_FENCE_BEFORE() asm volatile("tcgen05.fence::before_thread_sync;" ::: "memory")
#define TC_WAIT_LD() asm volatile("tcgen05.wait::ld.sync.aligned;" ::: "memory")
#define LDTM_X32(r, addr) \
    asm volatile("tcgen05.ld.sync.aligned.32x32b.x32.b32 " \
        "{%0,%1,%2,%3,%4,%5,%6,%7,%8,%9,%10,%11,%12,%13,%14,%15," \
        "%16,%17,%18,%19,%20,%21,%22,%23,%24,%25,%26,%27,%28,%29,%30,%31}, [%32];" \
        : "=r"((r)[0]),"=r"((r)[1]),"=r"((r)[2]),"=r"((r)[3]), \
          "=r"((r)[4]),"=r"((r)[5]),"=r"((r)[6]),"=r"((r)[7]), \
          "=r"((r)[8]),"=r"((r)[9]),"=r"((r)[10]),"=r"((r)[11]), \
          "=r"((r)[12]),"=r"((r)[13]),"=r"((r)[14]),"=r"((r)[15]), \
          "=r"((r)[16]),"=r"((r)[17]),"=r"((r)[18]),"=r"((r)[19]), \
          "=r"((r)[20]),"=r"((r)[21]),"=r"((r)[22]),"=r"((r)[23]), \
          "=r"((r)[24]),"=r"((r)[25]),"=r"((r)[26]),"=r"((r)[27]), \
          "=r"((r)[28]),"=r"((r)[29]),"=r"((r)[30]),"=r"((r)[31]) \
        : "r"(addr))

// SW128 K-major desc: LBO=1, SBO=64, version=1, layout=2
static __device__ __forceinline__ uint64_t make_desc(uint32_t addr) {
    const uint64_t base = (uint64_t(2) << 61) | (uint64_t(1) << 46)
                        | (uint64_t(64) << 32) | (uint64_t(1) << 16);
    return base | ((uint64_t)(addr >> 4) & 0x3FFF);
}
// tf32 SS MMA, cg1: D[128,128] += A[128,8] * B[128,8]^T
__device__ __forceinline__ void mma_tf32(uint32_t d, uint64_t ad, uint64_t bd,
                                         uint32_t idesc, uint32_t en) {
    asm volatile("{\n\t.reg .pred p;\n\tsetp.ne.u32 p, %5, 0;\n\t"
        "tcgen05.mma.cta_group::1.kind::tf32 [%0], %1, %2, %3, {%4,%4,%4,%4}, p;\n\t}"
        :: "r"(d), "l"(ad), "l"(bd), "r"(idesc), "r"(0u), "r"(en) : "memory");
}
#endif  // HAS_TC

__device__ __forceinline__ uint32_t swz(uint32_t o) { return o ^ ((o >> 3) & 0x70); }

__device__ __forceinline__ void cp16(uint32_t dst, const void* src, bool valid) {
    int sz = valid ? 16 : 0;
    asm volatile("cp.async.cg.shared.global [%0], [%1], 16, %2;"
                 :: "r"(dst), "l"(src), "r"(sz));
}

// ---------------- small kernels ----------------
__global__ void k_init() {
    g_sum_a = 0.0; g_sum_a2 = 0.0; g_sum_at = 0.0; g_F2 = 0.0; g_s2 = 0.0;
}

// 80 blocks x 50 rows each
__global__ void k_colsum_part(const float* __restrict__ W) {
    int k  = threadIdx.x;
    int m0 = blockIdx.x * 50;
    float s = 0.f;
    #pragma unroll 5
    for (int m = 0; m < 50; m++) s += W[(size_t)(m0 + m) * HID + k];
    g_sp[blockIdx.x][k] = s;
}

__global__ void k_colsum_reduce() {
    __shared__ double red[512];
    int k = threadIdx.x;
    float s = 0.f;
    #pragma unroll
    for (int j = 0; j < 80; j++) s += g_sp[j][k];
    g_s[k] = s;
    red[k] = (double)s * (double)s;
    __syncthreads();
    for (int o = 256; o > 0; o >>= 1) {
        if (k < o) red[k] += red[k + o];
        __syncthreads();
    }
    if (k == 0) g_s2 = red[0];
}

// 2 rows per warp: rows 0..3999 -> W, 4000..4511 -> F. 282 blocks x 256.
__global__ void k_rows2(const float* __restrict__ W, const float* __restrict__ F) {
    int warp = (blockIdx.x * blockDim.x + threadIdx.x) >> 5;
    int lane = threadIdx.x & 31;
    int r0 = warp * 2, r1 = r0 + 1;
    bool isW = (r0 < MC);
    const float* row0 = isW ? (W + (size_t)r0 * HID) : (F + (size_t)(r0 - MC) * HID);
    const float* row1 = isW ? (W + (size_t)r1 * HID) : (F + (size_t)(r1 - MC) * HID);
    float a0 = 0.f, a1 = 0.f, t0 = 0.f, t1 = 0.f;
    #pragma unroll
    for (int q = 0; q < 4; q++) {
        int i4 = lane + q * 32;
        float4 v0 = reinterpret_cast<const float4*>(row0)[i4];
        float4 v1 = reinterpret_cast<const float4*>(row1)[i4];
        a0 += v0.x*v0.x + v0.y*v0.y + v0.z*v0.z + v0.w*v0.w;
        a1 += v1.x*v1.x + v1.y*v1.y + v1.z*v1.z + v1.w*v1.w;
        if (isW) {
            float4 sv = reinterpret_cast<const float4*>(g_s)[i4];
            t0 += v0.x*sv.x + v0.y*sv.y + v0.z*sv.z + v0.w*sv.w;
            t1 += v1.x*sv.x + v1.y*sv.y + v1.z*sv.z + v1.w*sv.w;
        }
    }
    #pragma unroll
    for (int o = 16; o > 0; o >>= 1) {
        a0 += __shfl_down_sync(0xffffffffu, a0, o);
        a1 += __shfl_down_sync(0xffffffffu, a1, o);
        t0 += __shfl_down_sync(0xffffffffu, t0, o);
        t1 += __shfl_down_sync(0xffffffffu, t1, o);
    }
    if (lane == 0) {
        if (isW) {
            g_a[r0] = a0; g_a[r1] = a1;
            atomicAdd(&g_sum_a,  (double)a0 + (double)a1);
            atomicAdd(&g_sum_a2, (double)a0 * a0 + (double)a1 * a1);
            atomicAdd(&g_sum_at, (double)a0 * t0 + (double)a1 * t1);
        } else {
            g_fsq[r0 - MC] = a0; g_fsq[r1 - MC] = a1;
        }
    }
}

// ---------------- transpose: Wt[k][m] = W[m][k], Wt stride 4096 ----------------
// grid (16, 125) k-tiles x m-tiles of 32x32; block (32, 8)
__global__ void k_transpose(const float* __restrict__ W) {
    __shared__ float tile[32][33];
    int k0 = blockIdx.x * 32, m0 = blockIdx.y * 32;
    int x = threadIdx.x, y = threadIdx.y;
    #pragma unroll
    for (int i = 0; i < 4; i++)
        tile[y + i * 8][x] = W[(size_t)(m0 + y + i * 8) * HID + k0 + x];
    __syncthreads();
    #pragma unroll
    for (int i = 0; i < 4; i++)
        g_Wt[(size_t)(k0 + y + i * 8) * 4096 + m0 + x] = tile[x][y + i * 8];
}

// ---------------- pipeline layout (shared by both tcgen05 GEMMs) ----------------
#define STG       4
#define STG_BYTES 16384     // 128 rows x 128B
#define OFF_A     1024
#define OFF_B     (1024 + STG*STG_BYTES)
#define SMEM_TC   (1024 + 2*STG*STG_BYTES)
// idesc: cF32 | aTF32 | bTF32 | N=128 | M=128
#define IDESC_TF32 ((1u<<4) | (2u<<7) | (2u<<10) | (16u<<17) | (8u<<24))

// ---------------- tcgen05 Gram: G = Wt . Wt^T (contraction over m) ----------------
// grid (10, 5): symmetric tile x m-chunk of 800. 128 threads.
#define GK_NCHUNK 25

#if HAS_TC
__device__ __forceinline__ void gram_load_chunk(uint32_t sb, int stage, int c,
                                                int K0, int L0, int mbase, int tid) {
    int moff = mbase + c * 32;
    uint32_t dA = sb + OFF_A + stage * STG_BYTES;
    uint32_t dB = sb + OFF_B + stage * STG_BYTES;
    #pragma unroll
    for (int p = 0; p < 8; p++) {
        int idx = p * 128 + tid;
        int r = idx >> 3, seg = idx & 7;
        uint32_t off = swz((uint32_t)(r * 128 + seg * 16));
        cp16(dA + off, g_Wt + (size_t)(K0 + r) * 4096 + moff + seg * 4, true);
        cp16(dB + off, g_Wt + (size_t)(L0 + r) * 4096 + moff + seg * 4, true);
    }
}
#endif

__global__ void __launch_bounds__(128, 1) k_gram_tc() {
#if HAS_TC
    extern __shared__ char smem[];
    uint32_t sb = smem_u32(smem);
    int tid = threadIdx.x, wid = tid >> 5, lane = tid & 31;
    int t = blockIdx.x, z = blockIdx.y;
    int K0 = c_ti[t] * 128, L0 = c_tj[t] * 128, mbase = z * 800;

    if (tid < 4) MBAR_INIT(sb + tid * 8, 1);
    if (wid == 0) { TC_ALLOC(sb + 32, 128); TC_RELINQ(); }
    __syncthreads();
    uint32_t tmem;
    asm volatile("ld.shared.b32 %0, [%1];" : "=r"(tmem) : "r"(sb + 32));

    #pragma unroll
    for (int c0 = 0; c0 < 3; c0++) {
        gram_load_chunk(sb, c0, c0, K0, L0, mbase, tid);
        asm volatile("cp.async.commit_group;" ::: "memory");
    }

    uint32_t phv = 0;
    for (int c = 0; c < GK_NCHUNK; c++) {
        int s = c & 3;
        if (c + 3 < GK_NCHUNK) {
            int so = (c + 3) & 3;
            if (c >= 1) {
                MBAR_WAIT(sb + so * 8, (phv >> so) & 1u);
                phv ^= (1u << so);
            }
            gram_load_chunk(sb, so, c + 3, K0, L0, mbase, tid);
        }
        asm volatile("cp.async.commit_group;" ::: "memory");
        asm volatile("cp.async.wait_group 3;" ::: "memory");
        __syncthreads();
        if (wid == 0 && elect_one()) {
            asm volatile("fence.proxy.async.shared::cta;" ::: "memory");
            uint64_t ad = make_desc(sb + OFF_A + s * STG_BYTES);
            uint64_t bd = make_desc(sb + OFF_B + s * STG_BYTES);
            #pragma unroll
            for (int k = 0; k < 4; k++)
                mma_tf32(tmem, ad + k * 2, bd + k * 2, IDESC_TF32,
                         (c > 0 || k > 0) ? 1u : 0u);
            TC_COMMIT(sb + s * 8);
        }
    }
    __syncthreads();
    {
        int so = (GK_NCHUNK - 1) & 3;
        MBAR_WAIT(sb + so * 8, (phv >> so) & 1u);
    }
    TC_FENCE_AFTER();

    float* dst = g_G2 + ((size_t)(t * 5 + z) << 14);
    int row = wid * 32 + lane;
    #pragma unroll
    for (int j0 = 0; j0 < 128; j0 += 32) {
        uint32_t r[32];
        LDTM_X32(r, tmem + j0);
        TC_WAIT_LD();
        #pragma unroll
        for (int j4 = 0; j4 < 8; j4++) {
            float4 v = make_float4(__uint_as_float(r[j4*4+0]), __uint_as_float(r[j4*4+1]),
                                   __uint_as_float(r[j4*4+2]), __uint_as_float(r[j4*4+3]));
            *reinterpret_cast<float4*>(&dst[(size_t)row * 128 + j0 + j4 * 4]) = v;
        }
    }
    TC_FENCE_BEFORE();
    __syncthreads();
    if (wid == 0) TC_DEALLOC(tmem, 128);
#else
    // correct fallback (never selected on GB300)
    int t = blockIdx.x, z = blockIdx.y;
    int K0 = c_ti[t] * 128, L0 = c_tj[t] * 128, mbase = z * 800;
    float* dst = g_G2 + ((size_t)(t * 5 + z) << 14);
    for (int e = threadIdx.x; e < 16384; e += blockDim.x) {
        int k = K0 + (e >> 7), l = L0 + (e & 127);
        float acc = 0.f;
        for (int m = 0; m < 800; m++)
            acc = fmaf(g_Wt[(size_t)k * 4096 + mbase + m],
                       g_Wt[(size_t)l * 4096 + mbase + m], acc);
        dst[e] = acc;
    }
#endif
}

// ---------------- F2 = ||G||_F^2 (with symmetry weights) ----------------
__global__ void k_f2() {
    double acc = 0.0;
    for (int i = blockIdx.x * blockDim.x + threadIdx.x; i < 10 * 16384;
         i += gridDim.x * blockDim.x) {
        int t = i >> 14, e = i & 16383;
        float g = 0.f;
        #pragma unroll
        for (int z = 0; z < 5; z++) g += g_G2[((size_t)(t * 5 + z) << 14) + e];
        double w = (c_ti[t] == c_tj[t]) ? 1.0 : 2.0;
        acc += w * (double)g * (double)g;
    }
    __shared__ double sd[256];
    sd[threadIdx.x] = acc;
    __syncthreads();
    for (int o = 128; o > 0; o >>= 1) {
        if (threadIdx.x < o) sd[threadIdx.x] += sd[threadIdx.x + o];
        __syncthreads();
    }
    if (threadIdx.x == 0) atomicAdd(&g_F2, sd[0]);
}

// ---------------- tcgen05 tf32 GEMM: fw = W . F^T + fused epilogue ----------------
#define KC      32
#define NCHUNK  16

#if HAS_TC
__device__ __forceinline__ void fw_load_chunk(uint32_t sb, int stage, int c,
                                              const float* __restrict__ W,
                                              const float* __restrict__ F,
                                              int m0, int b0, int tid) {
    int kc = c * KC;
    uint32_t dA = sb + OFF_A + stage * STG_BYTES;
    uint32_t dB = sb + OFF_B + stage * STG_BYTES;
    #pragma unroll
    for (int p = 0; p < 8; p++) {
        int idx = p * 128 + tid;
        int r = idx >> 3, seg = idx & 7;
        uint32_t off = swz((uint32_t)(r * 128 + seg * 16));
        int m = m0 + r;
        bool v = (m < MC);
        cp16(dA + off, W + (size_t)(v ? m : 0) * HID + kc + seg * 4, v);
        cp16(dB + off, F + (size_t)(b0 + r) * HID + kc + seg * 4, true);
    }
}
#endif

__global__ void __launch_bounds__(128, 1) k_fw_tc(const float* __restrict__ F,
                                                  const float* __restrict__ W,
                                                  float* __restrict__ out) {
#if HAS_TC
    extern __shared__ char smem[];
    uint32_t sb = smem_u32(smem);
    int tid = threadIdx.x, wid = tid >> 5, lane = tid & 31;
    int m0 = blockIdx.x * 128, b0 = blockIdx.y * 128;

    if (tid < 4) MBAR_INIT(sb + tid * 8, 1);
    if (wid == 0) { TC_ALLOC(sb + 32, 128); TC_RELINQ(); }
    __syncthreads();
    uint32_t tmem;
    asm volatile("ld.shared.b32 %0, [%1];" : "=r"(tmem) : "r"(sb + 32));

    #pragma unroll
    for (int c0 = 0; c0 < 3; c0++) {
        fw_load_chunk(sb, c0, c0, W, F, m0, b0, tid);
        asm volatile("cp.async.commit_group;" ::: "memory");
    }

    uint32_t phv = 0;
    for (int c = 0; c < NCHUNK; c++) {
        int s = c & 3;
        if (c + 3 < NCHUNK) {
            int so = (c + 3) & 3;
            if (c >= 1) {
                MBAR_WAIT(sb + so * 8, (phv >> so) & 1u);
                phv ^= (1u << so);
            }
            fw_load_chunk(sb, so, c + 3, W, F, m0, b0, tid);
        }
        asm volatile("cp.async.commit_group;" ::: "memory");
        asm volatile("cp.async.wait_group 3;" ::: "memory");
        __syncthreads();
        if (wid == 0 && elect_one()) {
            asm volatile("fence.proxy.async.shared::cta;" ::: "memory");
            uint64_t ad = make_desc(sb + OFF_A + s * STG_BYTES);
            uint64_t bd = make_desc(sb + OFF_B + s * STG_BYTES);
            #pragma unroll
            for (int k = 0; k < 4; k++)
                mma_tf32(tmem, ad + k * 2, bd + k * 2, IDESC_TF32,
                         (c > 0 || k > 0) ? 1u : 0u);
            TC_COMMIT(sb + s * 8);
        }
    }
    __syncthreads();
    MBAR_WAIT(sb + 3 * 8, (phv >> 3) & 1u);
    TC_FENCE_AFTER();

    // epilogue: x = a_m - 2*fw ; min over 4-lane quads ; exp
    int m = m0 + wid * 32 + lane;
    float a = (m < MC) ? __ldg(&g_a[m]) : __int_as_float(0x7f800000);
    int grp = m >> 2;
    #pragma unroll
    for (int j0 = 0; j0 < 128; j0 += 32) {
        uint32_t r[32];
        LDTM_X32(r, tmem + j0);
        TC_WAIT_LD();
        #pragma unroll
        for (int jj = 0; jj < 32; jj++) {
            float fw = __uint_as_float(r[jj]);
            float x = fmaf(-2.f, fw, a);
            x = fminf(x, __shfl_xor_sync(0xffffffffu, x, 1));
            x = fminf(x, __shfl_xor_sync(0xffffffffu, x, 2));
            if ((lane & 3) == 0 && m < MC) {
                int b = b0 + j0 + jj;
                out[(size_t)b * (NCLS + 1) + grp] =
                    expf(-(__ldg(&g_fsq[b]) + x) * INV_SIGMA);
            }
        }
    }
    TC_FENCE_BEFORE();
    __syncthreads();
    if (wid == 0) TC_DEALLOC(tmem, 128);
#else
    // correct fallback (never selected on GB300)
    int tid = threadIdx.x;
    int m0 = blockIdx.x * 128, b0 = blockIdx.y * 128;
    int m = m0 + tid;
    if (m >= MC) return;
    float a = g_a[m];
    int grp = m >> 2;
    const float* wrow = W + (size_t)m * HID;
    for (int jb = 0; jb < 128; jb++) {
        int b = b0 + jb;
        const float* frow = F + (size_t)b * HID;
        float dot = 0.f;
        for (int k = 0; k < HID; k++) dot = fmaf(wrow[k], frow[k], dot);
        float x = fmaf(-2.f, dot, a);
        x = fminf(x, __shfl_xor_sync(0xffffffffu, x, 1));
        x = fminf(x, __shfl_xor_sync(0xffffffffu, x, 2));
        if ((tid & 3) == 0)
            out[(size_t)b * (NCLS + 1) + grp] =
                expf(-(g_fsq[b] + x) * INV_SIGMA);
    }
#endif
}

// ---------------- finalize rw ----------------
__global__ void k_finalize(float* __restrict__ out) {
    __shared__ float rw_s;
    if (threadIdx.x == 0) {
        double sum_a = g_sum_a, sum_a2 = g_sum_a2, sum_at = g_sum_at;
        double F2 = g_F2, s2 = g_s2;
        double mc = (double)MC;
        double denom = 2.0 / (mc * mc - mc);
        double S1 = mc * sum_a - s2;
        double mu = denom * S1;
        double S2 = mc * sum_a2 + sum_a * sum_a + 2.0 * F2 - 4.0 * sum_at;
        rw_s = (float)(denom * S2 - mu * mu);
    }
    __syncthreads();
    out[(size_t)threadIdx.x * (NCLS + 1) + NCLS] = rw_s;
}

extern "C" void kernel_launch(void* const* d_in, const int* in_sizes, int n_in,
                              void* d_out, int out_size) {
    const float* F = (const float*)d_in[0];   // [512,512]
    const float* W = (const float*)d_in[1];   // [4000,512]
    float* out = (float*)d_out;               // [512,1001]
    (void)in_sizes; (void)n_in; (void)out_size;

    static bool attr_set = false;
    if (!attr_set) {
        cudaFuncSetAttribute(k_fw_tc, cudaFuncAttributeMaxDynamicSharedMemorySize,
                             SMEM_TC);
        cudaFuncSetAttribute(k_gram_tc, cudaFuncAttributeMaxDynamicSharedMemorySize,
                             SMEM_TC);
        attr_set = true;
    }

    k_init<<<1, 1>>>();
    k_transpose<<<dim3(16, 125), dim3(32, 8)>>>(W);
    k_colsum_part<<<80, 512>>>(W);
    k_colsum_reduce<<<1, 512>>>();
    k_rows2<<<282, 256>>>(W, F);
    k_gram_tc<<<dim3(10, 5), 128, SMEM_TC>>>();
    k_f2<<<160, 256>>>();
    k_fw_tc<<<dim3(32, 4), 128, SMEM_TC>>>(F, W, out);
    k_finalize<<<1, 512>>>(out);
}

// round 8
// speedup vs baseline: 3.5676x; 1.1267x over previous
#include <cuda_runtime.h>
#include <math.h>
#include <stdint.h>

#define BATCH 512
#define HID   512
#define NCLS  1000
#define MC    4000
#define INV_SIGMA (1.0f/10.0f)

#if defined(__CUDA_ARCH__) && (__CUDA_ARCH__ == 1030) && defined(__CUDA_ARCH_FEAT_SM103_ALL)
#define HAS_TC 1
#else
#define HAS_TC 0
#endif

// ---------------- scratch ----------------
__device__ __align__(16) float g_a[4096];        // ||w_m||^2 (exact fp32)
__device__ __align__(16) float g_fsq[BATCH];     // ||f_b||^2
__device__ __align__(16) float g_s[HID];         // col sums of W (from rounded Wt)
__device__ __align__(16) float g_u[HID];         // u_k = sum_m a_m Wt[k,m]
__device__ __align__(16) float g_Wt[512*4096];   // W^T, tf32-RN-rounded, stride 4096
// Gram partials: 10 (ti<=tj) tiles x 5 m-chunks x 128x128
__device__ __align__(16) float g_G2[10*5*16384];
__device__ double g_f2p[160];                    // F2 partials per block

__constant__ int c_ti[10] = {0,0,0,0,1,1,1,2,2,3};
__constant__ int c_tj[10] = {0,1,2,3,1,2,3,2,3,3};

// ---------------- PTX helpers ----------------
__device__ __forceinline__ uint32_t smem_u32(const void* p) {
    uint32_t a;
    asm("{ .reg .u64 t; cvta.to.shared.u64 t, %1; cvt.u32.u64 %0, t; }"
        : "=r"(a) : "l"(p));
    return a;
}
__device__ __forceinline__ uint32_t elect_one() {
    uint32_t pred;
    asm volatile("{\n\t.reg .pred p;\n\telect.sync _|p, 0xFFFFFFFF;\n\t"
                 "selp.b32 %0, 1, 0, p;\n\t}" : "=r"(pred));
    return pred;
}
__device__ __forceinline__ float tf32_rn(float x) {
    float r;
    asm("cvt.rna.tf32.f32 %0, %1;" : "=f"(r) : "f"(x));
    return r;
}
#define MBAR_INIT(addr, cnt) \
    asm volatile("mbarrier.init.shared.b64 [%0], %1;" :: "r"(addr), "r"(cnt) : "memory")
#define MBAR_WAIT(addr, par) do { \
    uint32_t _m = (addr), _p = (par), _d; \
    asm volatile("{\n\t.reg .pred p;\n\t" \
        "mbarrier.try_wait.parity.acquire.cta.shared::cta.b64 p, [%1], %2;\n\t" \
        "selp.b32 %0, 1, 0, p;\n\t}" : "=r"(_d) : "r"(_m), "r"(_p) : "memory"); \
    if (!_d) { \
        asm volatile("{\n\t.reg .pred P1;\n\tWL%=:\n\t" \
            "mbarrier.try_wait.parity.acquire.cta.shared::cta.b64 P1, [%0], %1, 0x989680;\n\t" \
            "@P1 bra.uni WD%=;\n\tbra.uni WL%=;\n\tWD%=:\n\t}" \
            :: "r"(_m), "r"(_p) : "memory"); \
    } } while (0)

#if HAS_TC
#define TC_ALLOC(smem_addr, n) \
    asm volatile("tcgen05.alloc.cta_group::1.sync.aligned.shared::cta.b32 [%0], %1;" \
        :: "r"(smem_addr), "r"(n) : "memory")
#define TC_DEALLOC(tmem, n) \
    asm volatile("tcgen05.dealloc.cta_group::1.sync.aligned.b32 %0, %1;" :: "r"(tmem), "r"(n))
#define TC_RELINQ() \
    asm volatile("tcgen05.relinquish_alloc_permit.cta_group::1.sync.aligned;")
#define TC_COMMIT(mbar) \
    asm volatile("tcgen05.commit.cta_group::1.mbarrier::arrive::one.shared::cluster.b64 [%0];" \
        :: "r"(mbar) : "memory")
#define TC_FENCE_AFTER() asm volatile("tcgen05.fence::after_thread_sync;" ::: "memory")
#define TC_FENCE_BEFORE() asm volatile("tcgen05.fence::before_thread_sync;" ::: "memory")
#define TC_WAIT_LD() asm volatile("tcgen05.wait::ld.sync.aligned;" ::: "memory")
#define LDTM_X32(r, addr) \
    asm volatile("tcgen05.ld.sync.aligned.32x32b.x32.b32 " \
        "{%0,%1,%2,%3,%4,%5,%6,%7,%8,%9,%10,%11,%12,%13,%14,%15," \
        "%16,%17,%18,%19,%20,%21,%22,%23,%24,%25,%26,%27,%28,%29,%30,%31}, [%32];" \
        : "=r"((r)[0]),"=r"((r)[1]),"=r"((r)[2]),"=r"((r)[3]), \
          "=r"((r)[4]),"=r"((r)[5]),"=r"((r)[6]),"=r"((r)[7]), \
          "=r"((r)[8]),"=r"((r)[9]),"=r"((r)[10]),"=r"((r)[11]), \
          "=r"((r)[12]),"=r"((r)[13]),"=r"((r)[14]),"=r"((r)[15]), \
          "=r"((r)[16]),"=r"((r)[17]),"=r"((r)[18]),"=r"((r)[19]), \
          "=r"((r)[20]),"=r"((r)[21]),"=r"((r)[22]),"=r"((r)[23]), \
          "=r"((r)[24]),"=r"((r)[25]),"=r"((r)[26]),"=r"((r)[27]), \
          "=r"((r)[28]),"=r"((r)[29]),"=r"((r)[30]),"=r"((r)[31]) \
        : "r"(addr))

// SW128 K-major desc: LBO=1, SBO=64, version=1, layout=2
static __device__ __forceinline__ uint64_t make_desc(uint32_t addr) {
    const uint64_t base = (uint64_t(2) << 61) | (uint64_t(1) << 46)
                        | (uint64_t(64) << 32) | (uint64_t(1) << 16);
    return base | ((uint64_t)(addr >> 4) & 0x3FFF);
}
// tf32 SS MMA, cg1: D[128,128] += A[128,8] * B[128,8]^T
__device__ __forceinline__ void mma_tf32(uint32_t d, uint64_t ad, uint64_t bd,
                                         uint32_t idesc, uint32_t en) {
    asm volatile("{\n\t.reg .pred p;\n\tsetp.ne.u32 p, %5, 0;\n\t"
        "tcgen05.mma.cta_group::1.kind::tf32 [%0], %1, %2, %3, {%4,%4,%4,%4}, p;\n\t}"
        :: "r"(d), "l"(ad), "l"(bd), "r"(idesc), "r"(0u), "r"(en) : "memory");
}
#endif  // HAS_TC

__device__ __forceinline__ uint32_t swz(uint32_t o) { return o ^ ((o >> 3) & 0x70); }

__device__ __forceinline__ void cp16(uint32_t dst, const void* src, bool valid) {
    int sz = valid ? 16 : 0;
    asm volatile("cp.async.cg.shared.global [%0], [%1], 16, %2;"
                 :: "r"(dst), "l"(src), "r"(sz));
}

// ---------------- transpose + tf32-RN round: Wt[k][m] = rn(W[m][k]) ----------------
// grid (16, 125); block (32, 8)
__global__ void k_transpose(const float* __restrict__ W) {
    __shared__ float tile[32][33];
    int k0 = blockIdx.x * 32, m0 = blockIdx.y * 32;
    int x = threadIdx.x, y = threadIdx.y;
    #pragma unroll
    for (int i = 0; i < 4; i++)
        tile[y + i * 8][x] = W[(size_t)(m0 + y + i * 8) * HID + k0 + x];
    __syncthreads();
    #pragma unroll
    for (int i = 0; i < 4; i++)
        g_Wt[(size_t)(k0 + y + i * 8) * 4096 + m0 + x] = tf32_rn(tile[x][y + i * 8]);
}

// ---------------- k_pre: a_m = ||w_m||^2 (4 rows/warp), fsq ----------------
// 141 blocks x 256: 1128 warps x 4 rows = 4512
__global__ void k_pre(const float* __restrict__ W, const float* __restrict__ F) {
    int warp = (blockIdx.x * blockDim.x + threadIdx.x) >> 5;
    int lane = threadIdx.x & 31;
    int r0 = warp * 4;
    bool isW = (r0 < MC);                      // 4000 % 4 == 0: no straddle
    const float* base = isW ? W : F;
    int rb = isW ? r0 : (r0 - MC);
    float acc[4] = {0.f, 0.f, 0.f, 0.f};
    #pragma unroll
    for (int q = 0; q < 4; q++) {
        int i4 = lane + q * 32;
        #pragma unroll
        for (int j = 0; j < 4; j++) {
            float4 v = reinterpret_cast<const float4*>(base + (size_t)(rb + j) * HID)[i4];
            acc[j] += v.x*v.x + v.y*v.y + v.z*v.z + v.w*v.w;
        }
    }
    #pragma unroll
    for (int o = 16; o > 0; o >>= 1)
        #pragma unroll
        for (int j = 0; j < 4; j++)
            acc[j] += __shfl_down_sync(0xffffffffu, acc[j], o);
    if (lane == 0) {
        #pragma unroll
        for (int j = 0; j < 4; j++) {
            if (isW) g_a[r0 + j] = acc[j];
            else     g_fsq[rb + j] = acc[j];
        }
    }
}

// ---------------- k_su: s_k = sum_m Wt[k,m]; u_k = sum_m a_m Wt[k,m] ----------------
// 64 blocks x 256: warp per k (512 warps)
__global__ void k_su() {
    int k = (blockIdx.x * blockDim.x + threadIdx.x) >> 5;
    int lane = threadIdx.x & 31;
    const float4* row = reinterpret_cast<const float4*>(g_Wt + (size_t)k * 4096);
    const float4* av  = reinterpret_cast<const float4*>(g_a);
    float s = 0.f, u = 0.f;
    #pragma unroll 8
    for (int q = 0; q < 32; q++) {
        int i4 = lane + q * 32;
        if (i4 < 1000) {
            float4 w = row[i4];
            float4 a = av[i4];
            s += w.x + w.y + w.z + w.w;
            u += a.x*w.x + a.y*w.y + a.z*w.z + a.w*w.w;
        }
    }
    #pragma unroll
    for (int o = 16; o > 0; o >>= 1) {
        s += __shfl_down_sync(0xffffffffu, s, o);
        u += __shfl_down_sync(0xffffffffu, u, o);
    }
    if (lane == 0) { g_s[k] = s; g_u[k] = u; }
}

// ---------------- pipeline layout (shared by both tcgen05 GEMMs) ----------------
#define STG       4
#define STG_BYTES 16384     // 128 rows x 128B
#define OFF_A     1024
#define OFF_B     (1024 + STG*STG_BYTES)
#define SMEM_TC   (1024 + 2*STG*STG_BYTES)
// idesc: cF32 | aTF32 | bTF32 | N=128 | M=128
#define IDESC_TF32 ((1u<<4) | (2u<<7) | (2u<<10) | (16u<<17) | (8u<<24))

// ---------------- tcgen05 Gram: G = Wt . Wt^T (contraction over m) ----------------
#define GK_NCHUNK 25

#if HAS_TC
__device__ __forceinline__ void gram_load_chunk(uint32_t sb, int stage, int c,
                                                int K0, int L0, int mbase, int tid) {
    int moff = mbase + c * 32;
    uint32_t dA = sb + OFF_A + stage * STG_BYTES;
    uint32_t dB = sb + OFF_B + stage * STG_BYTES;
    #pragma unroll
    for (int p = 0; p < 8; p++) {
        int idx = p * 128 + tid;
        int r = idx >> 3, seg = idx & 7;
        uint32_t off = swz((uint32_t)(r * 128 + seg * 16));
        cp16(dA + off, g_Wt + (size_t)(K0 + r) * 4096 + moff + seg * 4, true);
        cp16(dB + off, g_Wt + (size_t)(L0 + r) * 4096 + moff + seg * 4, true);
    }
}
#endif

__global__ void __launch_bounds__(128, 1) k_gram_tc() {
#if HAS_TC
    extern __shared__ char smem[];
    uint32_t sb = smem_u32(smem);
    int tid = threadIdx.x, wid = tid >> 5, lane = tid & 31;
    int t = blockIdx.x, z = blockIdx.y;
    int K0 = c_ti[t] * 128, L0 = c_tj[t] * 128, mbase = z * 800;

    if (tid < 4) MBAR_INIT(sb + tid * 8, 1);
    if (wid == 0) { TC_ALLOC(sb + 32, 128); TC_RELINQ(); }
    __syncthreads();
    uint32_t tmem;
    asm volatile("ld.shared.b32 %0, [%1];" : "=r"(tmem) : "r"(sb + 32));

    #pragma unroll
    for (int c0 = 0; c0 < 3; c0++) {
        gram_load_chunk(sb, c0, c0, K0, L0, mbase, tid);
        asm volatile("cp.async.commit_group;" ::: "memory");
    }

    uint32_t phv = 0;
    for (int c = 0; c < GK_NCHUNK; c++) {
        int s = c & 3;
        if (c + 3 < GK_NCHUNK) {
            int so = (c + 3) & 3;
            if (c >= 1) {
                MBAR_WAIT(sb + so * 8, (phv >> so) & 1u);
                phv ^= (1u << so);
            }
            gram_load_chunk(sb, so, c + 3, K0, L0, mbase, tid);
        }
        asm volatile("cp.async.commit_group;" ::: "memory");
        asm volatile("cp.async.wait_group 3;" ::: "memory");
        __syncthreads();
        if (wid == 0 && elect_one()) {
            asm volatile("fence.proxy.async.shared::cta;" ::: "memory");
            uint64_t ad = make_desc(sb + OFF_A + s * STG_BYTES);
            uint64_t bd = make_desc(sb + OFF_B + s * STG_BYTES);
            #pragma unroll
            for (int k = 0; k < 4; k++)
                mma_tf32(tmem, ad + k * 2, bd + k * 2, IDESC_TF32,
                         (c > 0 || k > 0) ? 1u : 0u);
            TC_COMMIT(sb + s * 8);
        }
    }
    __syncthreads();
    {
        int so = (GK_NCHUNK - 1) & 3;
        MBAR_WAIT(sb + so * 8, (phv >> so) & 1u);
    }
    TC_FENCE_AFTER();

    float* dst = g_G2 + ((size_t)(t * 5 + z) << 14);
    int row = wid * 32 + lane;
    #pragma unroll
    for (int j0 = 0; j0 < 128; j0 += 32) {
        uint32_t r[32];
        LDTM_X32(r, tmem + j0);
        TC_WAIT_LD();
        #pragma unroll
        for (int j4 = 0; j4 < 8; j4++) {
            float4 v = make_float4(__uint_as_float(r[j4*4+0]), __uint_as_float(r[j4*4+1]),
                                   __uint_as_float(r[j4*4+2]), __uint_as_float(r[j4*4+3]));
            *reinterpret_cast<float4*>(&dst[(size_t)row * 128 + j0 + j4 * 4]) = v;
        }
    }
    TC_FENCE_BEFORE();
    __syncthreads();
    if (wid == 0) TC_DEALLOC(tmem, 128);
#else
    // correct fallback (never selected on GB300)
    int t = blockIdx.x, z = blockIdx.y;
    int K0 = c_ti[t] * 128, L0 = c_tj[t] * 128, mbase = z * 800;
    float* dst = g_G2 + ((size_t)(t * 5 + z) << 14);
    for (int e = threadIdx.x; e < 16384; e += blockDim.x) {
        int k = K0 + (e >> 7), l = L0 + (e & 127);
        float acc = 0.f;
        for (int m = 0; m < 800; m++)
            acc = fmaf(g_Wt[(size_t)k * 4096 + mbase + m],
                       g_Wt[(size_t)l * 4096 + mbase + m], acc);
        dst[e] = acc;
    }
#endif
}

// ---------------- F2 partials (no atomics) ----------------
__global__ void k_f2() {
    double acc = 0.0;
    for (int i = blockIdx.x * blockDim.x + threadIdx.x; i < 10 * 16384;
         i += gridDim.x * blockDim.x) {
        int t = i >> 14, e = i & 16383;
        float g = 0.f;
        #pragma unroll
        for (int z = 0; z < 5; z++) g += g_G2[((size_t)(t * 5 + z) << 14) + e];
        double w = (c_ti[t] == c_tj[t]) ? 1.0 : 2.0;
        acc += w * (double)g * (double)g;
    }
    __shared__ double sd[256];
    sd[threadIdx.x] = acc;
    __syncthreads();
    for (int o = 128; o > 0; o >>= 1) {
        if (threadIdx.x < o) sd[threadIdx.x] += sd[threadIdx.x + o];
        __syncthreads();
    }
    if (threadIdx.x == 0) g_f2p[blockIdx.x] = sd[0];
}

// ---------------- tcgen05 tf32 GEMM: fw = W . F^T + fused epilogue ----------------
#define KC      32
#define NCHUNK  16

#if HAS_TC
__device__ __forceinline__ void fw_load_chunk(uint32_t sb, int stage, int c,
                                              const float* __restrict__ W,
                                              const float* __restrict__ F,
                                              int m0, int b0, int tid) {
    int kc = c * KC;
    uint32_t dA = sb + OFF_A + stage * STG_BYTES;
    uint32_t dB = sb + OFF_B + stage * STG_BYTES;
    #pragma unroll
    for (int p = 0; p < 8; p++) {
        int idx = p * 128 + tid;
        int r = idx >> 3, seg = idx & 7;
        uint32_t off = swz((uint32_t)(r * 128 + seg * 16));
        int m = m0 + r;
        bool v = (m < MC);
        cp16(dA + off, W + (size_t)(v ? m : 0) * HID + kc + seg * 4, v);
        cp16(dB + off, F + (size_t)(b0 + r) * HID + kc + seg * 4, true);
    }
}
#endif

__global__ void __launch_bounds__(128, 1) k_fw_tc(const float* __restrict__ F,
                                                  const float* __restrict__ W,
                                                  float* __restrict__ out) {
#if HAS_TC
    extern __shared__ char smem[];
    uint32_t sb = smem_u32(smem);
    int tid = threadIdx.x, wid = tid >> 5, lane = tid & 31;
    int m0 = blockIdx.x * 128, b0 = blockIdx.y * 128;

    if (tid < 4) MBAR_INIT(sb + tid * 8, 1);
    if (wid == 0) { TC_ALLOC(sb + 32, 128); TC_RELINQ(); }
    __syncthreads();
    uint32_t tmem;
    asm volatile("ld.shared.b32 %0, [%1];" : "=r"(tmem) : "r"(sb + 32));

    #pragma unroll
    for (int c0 = 0; c0 < 3; c0++) {
        fw_load_chunk(sb, c0, c0, W, F, m0, b0, tid);
        asm volatile("cp.async.commit_group;" ::: "memory");
    }

    uint32_t phv = 0;
    for (int c = 0; c < NCHUNK; c++) {
        int s = c & 3;
        if (c + 3 < NCHUNK) {
            int so = (c + 3) & 3;
            if (c >= 1) {
                MBAR_WAIT(sb + so * 8, (phv >> so) & 1u);
                phv ^= (1u << so);
            }
            fw_load_chunk(sb, so, c + 3, W, F, m0, b0, tid);
        }
        asm volatile("cp.async.commit_group;" ::: "memory");
        asm volatile("cp.async.wait_group 3;" ::: "memory");
        __syncthreads();
        if (wid == 0 && elect_one()) {
            asm volatile("fence.proxy.async.shared::cta;" ::: "memory");
            uint64_t ad = make_desc(sb + OFF_A + s * STG_BYTES);
            uint64_t bd = make_desc(sb + OFF_B + s * STG_BYTES);
            #pragma unroll
            for (int k = 0; k < 4; k++)
                mma_tf32(tmem, ad + k * 2, bd + k * 2, IDESC_TF32,
                         (c > 0 || k > 0) ? 1u : 0u);
            TC_COMMIT(sb + s * 8);
        }
    }
    __syncthreads();
    MBAR_WAIT(sb + 3 * 8, (phv >> 3) & 1u);
    TC_FENCE_AFTER();

    // epilogue: x = a_m - 2*fw ; min over 4-lane quads ; exp
    int m = m0 + wid * 32 + lane;
    float a = (m < MC) ? __ldg(&g_a[m]) : __int_as_float(0x7f800000);
    int grp = m >> 2;
    #pragma unroll
    for (int j0 = 0; j0 < 128; j0 += 32) {
        uint32_t r[32];
        LDTM_X32(r, tmem + j0);
        TC_WAIT_LD();
        #pragma unroll
        for (int jj = 0; jj < 32; jj++) {
            float fw = __uint_as_float(r[jj]);
            float x = fmaf(-2.f, fw, a);
            x = fminf(x, __shfl_xor_sync(0xffffffffu, x, 1));
            x = fminf(x, __shfl_xor_sync(0xffffffffu, x, 2));
            if ((lane & 3) == 0 && m < MC) {
                int b = b0 + j0 + jj;
                out[(size_t)b * (NCLS + 1) + grp] =
                    expf(-(__ldg(&g_fsq[b]) + x) * INV_SIGMA);
            }
        }
    }
    TC_FENCE_BEFORE();
    __syncthreads();
    if (wid == 0) TC_DEALLOC(tmem, 128);
#else
    // correct fallback (never selected on GB300)
    int tid = threadIdx.x;
    int m0 = blockIdx.x * 128, b0 = blockIdx.y * 128;
    int m = m0 + tid;
    if (m >= MC) return;
    float a = g_a[m];
    int grp = m >> 2;
    const float* wrow = W + (size_t)m * HID;
    for (int jb = 0; jb < 128; jb++) {
        int b = b0 + jb;
        const float* frow = F + (size_t)b * HID;
        float dot = 0.f;
        for (int k = 0; k < HID; k++) dot = fmaf(wrow[k], frow[k], dot);
        float x = fmaf(-2.f, dot, a);
        x = fminf(x, __shfl_xor_sync(0xffffffffu, x, 1));
        x = fminf(x, __shfl_xor_sync(0xffffffffu, x, 2));
        if ((tid & 3) == 0)
            out[(size_t)b * (NCLS + 1) + grp] =
                expf(-(g_fsq[b] + x) * INV_SIGMA);
    }
#endif
}

// ---------------- finalize: all fp64 scalar reductions + rw column ----------------
__global__ void k_finalize(float* __restrict__ out) {
    __shared__ double sd[512];
    __shared__ float rw_s;
    int t = threadIdx.x;

    // per-thread partials
    double la = 0.0, la2 = 0.0;
    #pragma unroll
    for (int i = 0; i < 8; i++) {
        int idx = t * 8 + i;
        if (idx < MC) {
            double a = (double)g_a[idx];
            la += a; la2 += a * a;
        }
    }
    double ls2 = (double)g_s[t] * (double)g_s[t];
    double lat = (double)g_u[t] * (double)g_s[t];
    double lf2 = (t < 160) ? g_f2p[t] : 0.0;

    double res[5] = {la, la2, ls2, lat, lf2};
    double tot[5];
    #pragma unroll
    for (int q = 0; q < 5; q++) {
        __syncthreads();
        sd[t] = res[q];
        __syncthreads();
        for (int o = 256; o > 0; o >>= 1) {
            if (t < o) sd[t] += sd[t + o];
            __syncthreads();
        }
        tot[q] = sd[0];
    }

    if (t == 0) {
        double sum_a = tot[0], sum_a2 = tot[1], s2 = tot[2], sum_at = tot[3], F2 = tot[4];
        double mc = (double)MC;
        double denom = 2.0 / (mc * mc - mc);
        double S1 = mc * sum_a - s2;
        double mu = denom * S1;
        double S2 = mc * sum_a2 + sum_a * sum_a + 2.0 * F2 - 4.0 * sum_at;
        rw_s = (float)(denom * S2 - mu * mu);
    }
    __syncthreads();
    out[(size_t)t * (NCLS + 1) + NCLS] = rw_s;
}

extern "C" void kernel_launch(void* const* d_in, const int* in_sizes, int n_in,
                              void* d_out, int out_size) {
    const float* F = (const float*)d_in[0];   // [512,512]
    const float* W = (const float*)d_in[1];   // [4000,512]
    float* out = (float*)d_out;               // [512,1001]
    (void)in_sizes; (void)n_in; (void)out_size;

    static bool inited = false;
    static cudaStream_t s1;
    static cudaEvent_t evA, evT, evB;
    if (!inited) {
        cudaFuncSetAttribute(k_fw_tc, cudaFuncAttributeMaxDynamicSharedMemorySize,
                             SMEM_TC);
        cudaFuncSetAttribute(k_gram_tc, cudaFuncAttributeMaxDynamicSharedMemorySize,
                             SMEM_TC);
        cudaStreamCreateWithFlags(&s1, cudaStreamNonBlocking);
        cudaEventCreateWithFlags(&evA, cudaEventDisableTiming);
        cudaEventCreateWithFlags(&evT, cudaEventDisableTiming);
        cudaEventCreateWithFlags(&evB, cudaEventDisableTiming);
        inited = true;
    }

    // fork s1 from the capture-origin (default) stream
    cudaEventRecord(evA, 0);
    cudaStreamWaitEvent(s1, evA, 0);

    // chain 0: transpose -> gram -> f2
    k_transpose<<<dim3(16, 125), dim3(32, 8)>>>(W);
    cudaEventRecord(evT, 0);                  // Wt ready
    k_gram_tc<<<dim3(10, 5), 128, SMEM_TC>>>();
    k_f2<<<160, 256>>>();

    // chain 1: pre -> (wait Wt) su -> fw
    k_pre<<<141, 256, 0, s1>>>(W, F);
    cudaStreamWaitEvent(s1, evT, 0);
    k_su<<<64, 256, 0, s1>>>();
    k_fw_tc<<<dim3(32, 4), 128, SMEM_TC, s1>>>(F, W, out);
    cudaEventRecord(evB, s1);

    // join + finalize
    cudaStreamWaitEvent(0, evB, 0);
    k_finalize<<<1, 512>>>(out);
}